// round 13
// baseline (speedup 1.0000x reference)
#include <cuda_runtime.h>
#include <cuda_bf16.h>
#include <cstdint>

// Problem shape (fixed by reference): B=4, T=2048, N=1024, H=16, Dh=64
#define B_SZ   4
#define T_SEQ  2048
#define NDIM   1024
#define NH     16
#define DH     64
#define BH_TOT (B_SZ * NH)          // 64
#define M_ROWS (B_SZ * T_SEQ)       // 8192
#define K_DIM  1024

// Scratch (device globals — allocation-free per harness rules).
__device__ float g_Q[(size_t)BH_TOT * T_SEQ * DH];   // [bh][t][d]
__device__ float g_K[(size_t)BH_TOT * T_SEQ * DH];
__device__ float g_V[(size_t)BH_TOT * T_SEQ * DH];
__device__ float g_Y[(size_t)M_ROWS * NDIM];         // attention output [b*T+t][n]

// ---------------------------------------------------------------------------
// PTX helpers: ldmatrix + bf16 mma (fp32 accumulate)
// ---------------------------------------------------------------------------
__device__ __forceinline__ uint32_t smem_u32(const void* p) {
    return (uint32_t)__cvta_generic_to_shared(p);
}
__device__ __forceinline__ void ldsm_x4(uint32_t& r0, uint32_t& r1,
                                        uint32_t& r2, uint32_t& r3, uint32_t addr) {
    asm volatile("ldmatrix.sync.aligned.m8n8.x4.shared.b16 {%0,%1,%2,%3}, [%4];"
                 : "=r"(r0), "=r"(r1), "=r"(r2), "=r"(r3) : "r"(addr));
}
__device__ __forceinline__ void ldsm_x2_trans(uint32_t& r0, uint32_t& r1, uint32_t addr) {
    asm volatile("ldmatrix.sync.aligned.m8n8.x2.trans.shared.b16 {%0,%1}, [%2];"
                 : "=r"(r0), "=r"(r1) : "r"(addr));
}
__device__ __forceinline__ void mma16816(float* c, const uint32_t* a,
                                         uint32_t b0, uint32_t b1) {
    asm volatile(
        "mma.sync.aligned.m16n8k16.row.col.f32.bf16.bf16.f32 "
        "{%0,%1,%2,%3}, {%4,%5,%6,%7}, {%8,%9}, {%0,%1,%2,%3};"
        : "+f"(c[0]), "+f"(c[1]), "+f"(c[2]), "+f"(c[3])
        : "r"(a[0]), "r"(a[1]), "r"(a[2]), "r"(a[3]), "r"(b0), "r"(b1));
}

// fp32 pair -> (hi bf16x2, lo bf16x2), lo = residual
__device__ __forceinline__ void split2(float x, float y, uint32_t& hi, uint32_t& lo) {
    __nv_bfloat16 hx = __float2bfloat16(x);
    __nv_bfloat16 hy = __float2bfloat16(y);
    __nv_bfloat162 h; h.x = hx; h.y = hy;
    __nv_bfloat162 l = __floats2bfloat162_rn(x - __bfloat162float(hx),
                                             y - __bfloat162float(hy));
    hi = *reinterpret_cast<uint32_t*>(&h);
    lo = *reinterpret_cast<uint32_t*>(&l);
}

__device__ __forceinline__ void store_qkv(int r, int c, float v) {
    int b = r >> 11;               // /2048
    int t = r & 2047;
    int which = c >> 10;           // 0=Q 1=K 2=V
    int n = c & 1023;
    int h = n >> 6;
    int d = n & 63;
    float* dst = (which == 0) ? g_Q : (which == 1) ? g_K : g_V;
    dst[(((size_t)(b * NH + h) * T_SEQ) + t) * DH + d] = v;
}

// ---------------------------------------------------------------------------
// Tensor-core GEMM with bf16 hi/lo split (3-term compensated product).
// C[M=8192, N] = A[8192,1024] @ W[1024,N] + bias
// MODE 0: A = x param, epilogue scatters into g_Q/g_K/g_V
// MODE 1: A = g_Y,    epilogue writes Cout row-major
// CTA tile 128x128, BK=32, 256 threads (8 warps, each 64x32).
// ---------------------------------------------------------------------------
#define LDA 40    // halves per A smem row (32 + 8 pad) -> conflict-free ldmatrix
#define LDB 136   // halves per B smem row (128 + 8 pad)

template <int N, int MODE>
__global__ __launch_bounds__(256, 2)
void mma_gemm(const float* __restrict__ A, const float* __restrict__ W,
              const float* __restrict__ bias, float* __restrict__ Cout)
{
    __shared__ __nv_bfloat16 As_hi[128 * LDA];
    __shared__ __nv_bfloat16 As_lo[128 * LDA];
    __shared__ __nv_bfloat16 Bs_hi[32 * LDB];
    __shared__ __nv_bfloat16 Bs_lo[32 * LDB];

    const int tid  = threadIdx.x;
    const int lane = tid & 31;
    const int warp = tid >> 5;
    const int wm   = warp & 1;    // 0..1 -> row block of 64
    const int wn   = warp >> 1;   // 0..3 -> col block of 32
    const int row0 = blockIdx.y * 128;
    const int col0 = blockIdx.x * 128;

    const float* Asrc = (MODE == 0) ? A : (const float*)g_Y;

    float acc[4][4][4];
#pragma unroll
    for (int mt = 0; mt < 4; mt++)
#pragma unroll
        for (int nt = 0; nt < 4; nt++)
#pragma unroll
            for (int e = 0; e < 4; e++) acc[mt][nt][e] = 0.f;

    // fill-phase indices
    const int arow = tid >> 1;            // 0..127
    const int ac0  = (tid & 1) * 16;      // 0 or 16
    const int brow = tid >> 3;            // 0..31
    const int bc0  = (tid & 7) * 16;      // 0..112

    // ldmatrix base addresses (bytes, shared space)
    const int a_r = lane & 15;
    const int a_c = (lane >> 4) << 3;
    const uint32_t a_hi_base = smem_u32(&As_hi[(wm * 64 + a_r) * LDA + a_c]);
    const uint32_t a_lo_base = smem_u32(&As_lo[(wm * 64 + a_r) * LDA + a_c]);
    const int b_k = lane & 15;
    const uint32_t b_hi_base = smem_u32(&Bs_hi[b_k * LDB + wn * 32]);
    const uint32_t b_lo_base = smem_u32(&Bs_lo[b_k * LDB + wn * 32]);

    const float* ap = Asrc + (size_t)(row0 + arow) * K_DIM + ac0;
    const float* bp = W + (size_t)brow * N + col0 + bc0;

#pragma unroll 1
    for (int k0 = 0; k0 < K_DIM; k0 += 32) {
        // ---- fill A tile (fp32 -> hi/lo bf16) ----
#pragma unroll
        for (int j = 0; j < 4; j++) {
            float4 v = *(const float4*)(ap + k0 + j * 4);
            uint32_t h0, l0, h1, l1;
            split2(v.x, v.y, h0, l0);
            split2(v.z, v.w, h1, l1);
            int off = arow * LDA + ac0 + j * 4;
            *(uint2*)&As_hi[off] = make_uint2(h0, h1);
            *(uint2*)&As_lo[off] = make_uint2(l0, l1);
        }
        // ---- fill B tile ----
#pragma unroll
        for (int j = 0; j < 4; j++) {
            float4 v = *(const float4*)(bp + (size_t)k0 * N + j * 4);
            uint32_t h0, l0, h1, l1;
            split2(v.x, v.y, h0, l0);
            split2(v.z, v.w, h1, l1);
            int off = brow * LDB + bc0 + j * 4;
            *(uint2*)&Bs_hi[off] = make_uint2(h0, h1);
            *(uint2*)&Bs_lo[off] = make_uint2(l0, l1);
        }
        __syncthreads();

        // ---- MMA phase: two k16 steps ----
#pragma unroll
        for (int ks = 0; ks < 2; ks++) {
            uint32_t bh[4][2], bl[4][2];
#pragma unroll
            for (int nt = 0; nt < 4; nt++) {
                uint32_t boff = (uint32_t)((ks * 16) * LDB + nt * 8) * 2u;
                ldsm_x2_trans(bh[nt][0], bh[nt][1], b_hi_base + boff);
                ldsm_x2_trans(bl[nt][0], bl[nt][1], b_lo_base + boff);
            }
#pragma unroll
            for (int mt = 0; mt < 4; mt++) {
                uint32_t ah[4], al[4];
                uint32_t aoff = (uint32_t)(mt * 16 * LDA + ks * 16) * 2u;
                ldsm_x4(ah[0], ah[1], ah[2], ah[3], a_hi_base + aoff);
                ldsm_x4(al[0], al[1], al[2], al[3], a_lo_base + aoff);
#pragma unroll
                for (int nt = 0; nt < 4; nt++) {
                    mma16816(acc[mt][nt], ah, bh[nt][0], bh[nt][1]);  // hi*hi
                    mma16816(acc[mt][nt], ah, bl[nt][0], bl[nt][1]);  // hi*lo
                    mma16816(acc[mt][nt], al, bh[nt][0], bh[nt][1]);  // lo*hi
                }
            }
        }
        __syncthreads();
    }

    // ---- epilogue ----
    const int r_lane = lane >> 2;          // 0..7
    const int c_lane = (lane & 3) * 2;     // 0,2,4,6
#pragma unroll
    for (int mt = 0; mt < 4; mt++) {
#pragma unroll
        for (int nt = 0; nt < 4; nt++) {
            int c = col0 + wn * 32 + nt * 8 + c_lane;
            float b0 = bias[c], b1 = bias[c + 1];
#pragma unroll
            for (int h2 = 0; h2 < 2; h2++) {
                int r = row0 + wm * 64 + mt * 16 + r_lane + h2 * 8;
                float v0 = acc[mt][nt][h2 * 2 + 0] + b0;
                float v1 = acc[mt][nt][h2 * 2 + 1] + b1;
                if (MODE == 0) {
                    store_qkv(r, c, v0);
                    store_qkv(r, c + 1, v1);
                } else {
                    Cout[(size_t)r * N + c]     = v0;
                    Cout[(size_t)r * N + c + 1] = v1;
                }
            }
        }
    }
}

// ---------------------------------------------------------------------------
// Causal flash attention, fp32 (unchanged from best passing kernel).
// ---------------------------------------------------------------------------
#define APAD 68
#define ABUF (DH * APAD)
#define ATTN_SMEM (4 * ABUF * (int)sizeof(float))

__global__ __launch_bounds__(256, 3)
void attn_kernel()
{
    extern __shared__ float smem[];
    float* Qt = smem;               // [d][q]
    float* Kt = smem + ABUF;        // [d][k]
    float* Vs = smem + 2 * ABUF;    // [k][d]
    float* Pt = smem + 3 * ABUF;    // [k][q]

    const int tid = threadIdx.x;
    const int qb  = blockIdx.x;
    const int bh  = blockIdx.y;
    const int q0  = qb * 64;

    const float* Qg = g_Q + (size_t)bh * T_SEQ * DH;
    const float* Kg = g_K + (size_t)bh * T_SEQ * DH;
    const float* Vg = g_V + (size_t)bh * T_SEQ * DH;

#pragma unroll
    for (int it = 0; it < 4; it++) {
        int s   = tid + it * 256;
        int row = s >> 4;
        int c4  = (s & 15) << 2;
        float4 v = *(const float4*)(Qg + (size_t)(q0 + row) * DH + c4);
        Qt[(c4 + 0) * APAD + row] = v.x * 0.125f;
        Qt[(c4 + 1) * APAD + row] = v.y * 0.125f;
        Qt[(c4 + 2) * APAD + row] = v.z * 0.125f;
        Qt[(c4 + 3) * APAD + row] = v.w * 0.125f;
    }

    const int ty = tid >> 4;
    const int tx = tid & 15;

    float acc[4][4];
    float mrow[4], lrow[4];
#pragma unroll
    for (int i = 0; i < 4; i++) {
        mrow[i] = -1e30f;
        lrow[i] = 0.f;
#pragma unroll
        for (int j = 0; j < 4; j++) acc[i][j] = 0.f;
    }

    for (int jb = 0; jb <= qb; jb++) {
        const int k0 = jb * 64;
        __syncthreads();
#pragma unroll
        for (int it = 0; it < 4; it++) {
            int s   = tid + it * 256;
            int row = s >> 4;
            int c4  = (s & 15) << 2;
            float4 kv = *(const float4*)(Kg + (size_t)(k0 + row) * DH + c4);
            Kt[(c4 + 0) * APAD + row] = kv.x;
            Kt[(c4 + 1) * APAD + row] = kv.y;
            Kt[(c4 + 2) * APAD + row] = kv.z;
            Kt[(c4 + 3) * APAD + row] = kv.w;
            *(float4*)&Vs[row * APAD + c4] =
                *(const float4*)(Vg + (size_t)(k0 + row) * DH + c4);
        }
        __syncthreads();

        float S[4][4];
#pragma unroll
        for (int i = 0; i < 4; i++)
#pragma unroll
            for (int j = 0; j < 4; j++) S[i][j] = 0.f;

#pragma unroll 16
        for (int d = 0; d < DH; d++) {
            float4 qv = *(float4*)&Qt[d * APAD + ty * 4];
            float4 kv = *(float4*)&Kt[d * APAD + tx * 4];
            float qr[4] = {qv.x, qv.y, qv.z, qv.w};
            float kr[4] = {kv.x, kv.y, kv.z, kv.w};
#pragma unroll
            for (int i = 0; i < 4; i++)
#pragma unroll
                for (int j = 0; j < 4; j++)
                    S[i][j] = fmaf(qr[i], kr[j], S[i][j]);
        }

        if (jb == qb) {
#pragma unroll
            for (int i = 0; i < 4; i++)
#pragma unroll
                for (int j = 0; j < 4; j++)
                    if ((k0 + tx * 4 + j) > (q0 + ty * 4 + i)) S[i][j] = -1e30f;
        }

#pragma unroll
        for (int i = 0; i < 4; i++) {
            float m = fmaxf(fmaxf(S[i][0], S[i][1]), fmaxf(S[i][2], S[i][3]));
            m = fmaxf(m, __shfl_xor_sync(0xffffffffu, m, 8));
            m = fmaxf(m, __shfl_xor_sync(0xffffffffu, m, 4));
            m = fmaxf(m, __shfl_xor_sync(0xffffffffu, m, 2));
            m = fmaxf(m, __shfl_xor_sync(0xffffffffu, m, 1));
            float mnew = fmaxf(mrow[i], m);
            float corr = __expf(mrow[i] - mnew);
            mrow[i] = mnew;

            float ls = 0.f;
#pragma unroll
            for (int j = 0; j < 4; j++) {
                float p = __expf(S[i][j] - mnew);
                S[i][j] = p;
                ls += p;
            }
            ls += __shfl_xor_sync(0xffffffffu, ls, 8);
            ls += __shfl_xor_sync(0xffffffffu, ls, 4);
            ls += __shfl_xor_sync(0xffffffffu, ls, 2);
            ls += __shfl_xor_sync(0xffffffffu, ls, 1);
            lrow[i] = lrow[i] * corr + ls;

#pragma unroll
            for (int j = 0; j < 4; j++) {
                acc[i][j] *= corr;
                Pt[(tx * 4 + j) * APAD + ty * 4 + i] = S[i][j];
            }
        }
        __syncthreads();

#pragma unroll 16
        for (int k = 0; k < 64; k++) {
            float4 pv = *(float4*)&Pt[k * APAD + ty * 4];
            float4 vv = *(float4*)&Vs[k * APAD + tx * 4];
            float pr[4] = {pv.x, pv.y, pv.z, pv.w};
            float vr[4] = {vv.x, vv.y, vv.z, vv.w};
#pragma unroll
            for (int i = 0; i < 4; i++)
#pragma unroll
                for (int j = 0; j < 4; j++)
                    acc[i][j] = fmaf(pr[i], vr[j], acc[i][j]);
        }
    }

    const int b = bh >> 4;
    const int h = bh & 15;
#pragma unroll
    for (int i = 0; i < 4; i++) {
        float inv = 1.f / lrow[i];
        size_t t = (size_t)q0 + ty * 4 + i;
#pragma unroll
        for (int j = 0; j < 4; j++) {
            g_Y[((size_t)b * T_SEQ + t) * NDIM + h * DH + tx * 4 + j] =
                acc[i][j] * inv;
        }
    }
}

// ---------------------------------------------------------------------------
extern "C" void kernel_launch(void* const* d_in, const int* in_sizes, int n_in,
                              void* d_out, int out_size)
{
    (void)in_sizes; (void)n_in; (void)out_size;
    const float* x      = (const float*)d_in[0];   // [4,2048,1024]
    const float* W_attn = (const float*)d_in[1];   // [1024,3072]
    const float* b_attn = (const float*)d_in[2];   // [3072]
    const float* W_proj = (const float*)d_in[3];   // [1024,1024]
    const float* b_proj = (const float*)d_in[4];   // [1024]
    float* out = (float*)d_out;                    // [4,2048,1024]

    cudaFuncSetAttribute(attn_kernel,
                         cudaFuncAttributeMaxDynamicSharedMemorySize, ATTN_SMEM);

    // 1) QKV GEMM (tensor cores, bf16 split) + scatter to [bh][t][d]
    mma_gemm<3072, 0><<<dim3(3072 / 128, M_ROWS / 128), 256>>>(
        x, W_attn, b_attn, nullptr);

    // 2) Causal flash attention
    attn_kernel<<<dim3(T_SEQ / 64, BH_TOT), 256, ATTN_SMEM>>>();

    // 3) Output projection (tensor cores, bf16 split)
    mma_gemm<1024, 1><<<dim3(1024 / 128, M_ROWS / 128), 256>>>(
        nullptr, W_proj, b_proj, out);
}

// round 14
// speedup vs baseline: 1.7727x; 1.7727x over previous
#include <cuda_runtime.h>
#include <cuda_bf16.h>
#include <cstdint>

// Problem shape (fixed by reference): B=4, T=2048, N=1024, H=16, Dh=64
#define B_SZ   4
#define T_SEQ  2048
#define NDIM   1024
#define NH     16
#define DH     64
#define BH_TOT (B_SZ * NH)          // 64
#define M_ROWS (B_SZ * T_SEQ)       // 8192
#define K_DIM  1024

// Scratch (device globals — allocation-free per harness rules).
__device__ float g_Q[(size_t)BH_TOT * T_SEQ * DH];   // [bh][t][d]
__device__ float g_K[(size_t)BH_TOT * T_SEQ * DH];
__device__ float g_V[(size_t)BH_TOT * T_SEQ * DH];
__device__ float g_Y[(size_t)M_ROWS * NDIM];         // attention output [b*T+t][n]

// ---------------------------------------------------------------------------
// PTX helpers: ldmatrix + bf16 mma (fp32 accumulate)
// ---------------------------------------------------------------------------
__device__ __forceinline__ uint32_t smem_u32(const void* p) {
    return (uint32_t)__cvta_generic_to_shared(p);
}
__device__ __forceinline__ void ldsm_x4(uint32_t& r0, uint32_t& r1,
                                        uint32_t& r2, uint32_t& r3, uint32_t addr) {
    asm volatile("ldmatrix.sync.aligned.m8n8.x4.shared.b16 {%0,%1,%2,%3}, [%4];"
                 : "=r"(r0), "=r"(r1), "=r"(r2), "=r"(r3) : "r"(addr));
}
__device__ __forceinline__ void ldsm_x2(uint32_t& r0, uint32_t& r1, uint32_t addr) {
    asm volatile("ldmatrix.sync.aligned.m8n8.x2.shared.b16 {%0,%1}, [%2];"
                 : "=r"(r0), "=r"(r1) : "r"(addr));
}
__device__ __forceinline__ void ldsm_x2_trans(uint32_t& r0, uint32_t& r1, uint32_t addr) {
    asm volatile("ldmatrix.sync.aligned.m8n8.x2.trans.shared.b16 {%0,%1}, [%2];"
                 : "=r"(r0), "=r"(r1) : "r"(addr));
}
__device__ __forceinline__ void mma16816(float* c, const uint32_t* a,
                                         uint32_t b0, uint32_t b1) {
    asm volatile(
        "mma.sync.aligned.m16n8k16.row.col.f32.bf16.bf16.f32 "
        "{%0,%1,%2,%3}, {%4,%5,%6,%7}, {%8,%9}, {%0,%1,%2,%3};"
        : "+f"(c[0]), "+f"(c[1]), "+f"(c[2]), "+f"(c[3])
        : "r"(a[0]), "r"(a[1]), "r"(a[2]), "r"(a[3]), "r"(b0), "r"(b1));
}

// fp32 pair -> (hi bf16x2, lo bf16x2), lo = residual
__device__ __forceinline__ void split2(float x, float y, uint32_t& hi, uint32_t& lo) {
    __nv_bfloat16 hx = __float2bfloat16(x);
    __nv_bfloat16 hy = __float2bfloat16(y);
    __nv_bfloat162 h; h.x = hx; h.y = hy;
    __nv_bfloat162 l = __floats2bfloat162_rn(x - __bfloat162float(hx),
                                             y - __bfloat162float(hy));
    hi = *reinterpret_cast<uint32_t*>(&h);
    lo = *reinterpret_cast<uint32_t*>(&l);
}

__device__ __forceinline__ void store_qkv(int r, int c, float v) {
    int b = r >> 11;               // /2048
    int t = r & 2047;
    int which = c >> 10;           // 0=Q 1=K 2=V
    int n = c & 1023;
    int h = n >> 6;
    int d = n & 63;
    float* dst = (which == 0) ? g_Q : (which == 1) ? g_K : g_V;
    dst[(((size_t)(b * NH + h) * T_SEQ) + t) * DH + d] = v;
}

// ---------------------------------------------------------------------------
// Tensor-core GEMM with bf16 hi/lo split (3-term compensated product).
// (unchanged from Round 12 — passing at rel_err 1.4e-5)
// ---------------------------------------------------------------------------
#define LDA 40
#define LDB 136

template <int N, int MODE>
__global__ __launch_bounds__(256, 2)
void mma_gemm(const float* __restrict__ A, const float* __restrict__ W,
              const float* __restrict__ bias, float* __restrict__ Cout)
{
    __shared__ __nv_bfloat16 As_hi[128 * LDA];
    __shared__ __nv_bfloat16 As_lo[128 * LDA];
    __shared__ __nv_bfloat16 Bs_hi[32 * LDB];
    __shared__ __nv_bfloat16 Bs_lo[32 * LDB];

    const int tid  = threadIdx.x;
    const int lane = tid & 31;
    const int warp = tid >> 5;
    const int wm   = warp & 1;
    const int wn   = warp >> 1;
    const int row0 = blockIdx.y * 128;
    const int col0 = blockIdx.x * 128;

    const float* Asrc = (MODE == 0) ? A : (const float*)g_Y;

    float acc[4][4][4];
#pragma unroll
    for (int mt = 0; mt < 4; mt++)
#pragma unroll
        for (int nt = 0; nt < 4; nt++)
#pragma unroll
            for (int e = 0; e < 4; e++) acc[mt][nt][e] = 0.f;

    const int arow = tid >> 1;
    const int ac0  = (tid & 1) * 16;
    const int brow = tid >> 3;
    const int bc0  = (tid & 7) * 16;

    const int a_r = lane & 15;
    const int a_c = (lane >> 4) << 3;
    const uint32_t a_hi_base = smem_u32(&As_hi[(wm * 64 + a_r) * LDA + a_c]);
    const uint32_t a_lo_base = smem_u32(&As_lo[(wm * 64 + a_r) * LDA + a_c]);
    const int b_k = lane & 15;
    const uint32_t b_hi_base = smem_u32(&Bs_hi[b_k * LDB + wn * 32]);
    const uint32_t b_lo_base = smem_u32(&Bs_lo[b_k * LDB + wn * 32]);

    const float* ap = Asrc + (size_t)(row0 + arow) * K_DIM + ac0;
    const float* bp = W + (size_t)brow * N + col0 + bc0;

#pragma unroll 1
    for (int k0 = 0; k0 < K_DIM; k0 += 32) {
#pragma unroll
        for (int j = 0; j < 4; j++) {
            float4 v = *(const float4*)(ap + k0 + j * 4);
            uint32_t h0, l0, h1, l1;
            split2(v.x, v.y, h0, l0);
            split2(v.z, v.w, h1, l1);
            int off = arow * LDA + ac0 + j * 4;
            *(uint2*)&As_hi[off] = make_uint2(h0, h1);
            *(uint2*)&As_lo[off] = make_uint2(l0, l1);
        }
#pragma unroll
        for (int j = 0; j < 4; j++) {
            float4 v = *(const float4*)(bp + (size_t)k0 * N + j * 4);
            uint32_t h0, l0, h1, l1;
            split2(v.x, v.y, h0, l0);
            split2(v.z, v.w, h1, l1);
            int off = brow * LDB + bc0 + j * 4;
            *(uint2*)&Bs_hi[off] = make_uint2(h0, h1);
            *(uint2*)&Bs_lo[off] = make_uint2(l0, l1);
        }
        __syncthreads();

#pragma unroll
        for (int ks = 0; ks < 2; ks++) {
            uint32_t bh[4][2], bl[4][2];
#pragma unroll
            for (int nt = 0; nt < 4; nt++) {
                uint32_t boff = (uint32_t)((ks * 16) * LDB + nt * 8) * 2u;
                ldsm_x2_trans(bh[nt][0], bh[nt][1], b_hi_base + boff);
                ldsm_x2_trans(bl[nt][0], bl[nt][1], b_lo_base + boff);
            }
#pragma unroll
            for (int mt = 0; mt < 4; mt++) {
                uint32_t ah[4], al[4];
                uint32_t aoff = (uint32_t)(mt * 16 * LDA + ks * 16) * 2u;
                ldsm_x4(ah[0], ah[1], ah[2], ah[3], a_hi_base + aoff);
                ldsm_x4(al[0], al[1], al[2], al[3], a_lo_base + aoff);
#pragma unroll
                for (int nt = 0; nt < 4; nt++) {
                    mma16816(acc[mt][nt], ah, bh[nt][0], bh[nt][1]);
                    mma16816(acc[mt][nt], ah, bl[nt][0], bl[nt][1]);
                    mma16816(acc[mt][nt], al, bh[nt][0], bh[nt][1]);
                }
            }
        }
        __syncthreads();
    }

    const int r_lane = lane >> 2;
    const int c_lane = (lane & 3) * 2;
#pragma unroll
    for (int mt = 0; mt < 4; mt++) {
#pragma unroll
        for (int nt = 0; nt < 4; nt++) {
            int c = col0 + wn * 32 + nt * 8 + c_lane;
            float b0 = bias[c], b1 = bias[c + 1];
#pragma unroll
            for (int h2 = 0; h2 < 2; h2++) {
                int r = row0 + wm * 64 + mt * 16 + r_lane + h2 * 8;
                float v0 = acc[mt][nt][h2 * 2 + 0] + b0;
                float v1 = acc[mt][nt][h2 * 2 + 1] + b1;
                if (MODE == 0) {
                    store_qkv(r, c, v0);
                    store_qkv(r, c + 1, v1);
                } else {
                    Cout[(size_t)r * N + c]     = v0;
                    Cout[(size_t)r * N + c + 1] = v1;
                }
            }
        }
    }
}

// ---------------------------------------------------------------------------
// Tensor-core causal flash attention, bf16 hi/lo split on both matmuls.
// CTA = 128 queries x one (b,h). 8 warps x 16 query rows. 64-key blocks.
// Softmax in exp2 domain (log2e folded into Q prescale).
// ---------------------------------------------------------------------------
#define LDQS 72   // halves per smem row (64 + 8 pad) -> 9x16B stride, conflict-free
#define Q_HALVES (128 * LDQS)
#define KV_HALVES (64 * LDQS)
#define ATTN_SMEM ((2 * Q_HALVES + 4 * KV_HALVES) * 2)   // 73728 bytes

__global__ __launch_bounds__(256, 2)
void attn_mma_kernel()
{
    extern __shared__ __nv_bfloat16 sm[];
    __nv_bfloat16* Qh = sm;
    __nv_bfloat16* Ql = Qh + Q_HALVES;
    __nv_bfloat16* Kh = Ql + Q_HALVES;
    __nv_bfloat16* Kl = Kh + KV_HALVES;
    __nv_bfloat16* Vh = Kl + KV_HALVES;
    __nv_bfloat16* Vl = Vh + KV_HALVES;

    const int tid  = threadIdx.x;
    const int lane = tid & 31;
    const int warp = tid >> 5;
    const int qt   = blockIdx.x;        // 0..15 (128-query tiles)
    const int bh   = blockIdx.y;        // 0..63
    const int q0   = qt * 128;
    const int qw0  = q0 + warp * 16;    // warp's first query row

    const float* Qg = g_Q + (size_t)bh * T_SEQ * DH;
    const float* Kg = g_K + (size_t)bh * T_SEQ * DH;
    const float* Vg = g_V + (size_t)bh * T_SEQ * DH;

    // ---- load Q tile (prescale by 0.125 * log2(e), split hi/lo) ----
    const float qscale = 0.125f * 1.4426950408889634f;
#pragma unroll
    for (int it = 0; it < 8; it++) {
        int s   = tid + it * 256;        // 2048 float4 slots
        int row = s >> 4;
        int c4  = (s & 15) << 2;
        float4 v = *(const float4*)(Qg + (size_t)(q0 + row) * DH + c4);
        uint32_t h0, l0, h1, l1;
        split2(v.x * qscale, v.y * qscale, h0, l0);
        split2(v.z * qscale, v.w * qscale, h1, l1);
        int off = row * LDQS + c4;
        *(uint2*)&Qh[off] = make_uint2(h0, h1);
        *(uint2*)&Ql[off] = make_uint2(l0, l1);
    }

    // ldmatrix base addresses
    const uint32_t q_hi_base = smem_u32(&Qh[(warp * 16 + (lane & 15)) * LDQS + ((lane >> 4) << 3)]);
    const uint32_t q_lo_base = smem_u32(&Ql[(warp * 16 + (lane & 15)) * LDQS + ((lane >> 4) << 3)]);
    const uint32_t k_hi_base = smem_u32(&Kh[(lane & 7) * LDQS + (((lane >> 3) & 1) << 3)]);
    const uint32_t k_lo_base = smem_u32(&Kl[(lane & 7) * LDQS + (((lane >> 3) & 1) << 3)]);
    const uint32_t v_hi_base = smem_u32(&Vh[(lane & 15) * LDQS]);
    const uint32_t v_lo_base = smem_u32(&Vl[(lane & 15) * LDQS]);

    float Ov[8][4];
#pragma unroll
    for (int nt = 0; nt < 8; nt++)
#pragma unroll
        for (int e = 0; e < 4; e++) Ov[nt][e] = 0.f;
    float mrow[2] = {-1e30f, -1e30f};
    float lrow[2] = {0.f, 0.f};

    const int nkb = 2 * (qt + 1);       // causal key-block count

    for (int jb = 0; jb < nkb; jb++) {
        const int k0 = jb * 64;
        __syncthreads();                 // prev PV done before overwrite
        // ---- load K,V block (split hi/lo) ----
#pragma unroll
        for (int it = 0; it < 8; it++) {
            int s = tid + it * 256;      // 2048 slots: 1024 K + 1024 V
            int row = (s >> 4) & 63;
            int c4  = (s & 15) << 2;
            const float* src = (s < 1024) ? Kg : Vg;
            __nv_bfloat16* dh = (s < 1024) ? Kh : Vh;
            __nv_bfloat16* dl = (s < 1024) ? Kl : Vl;
            float4 v = *(const float4*)(src + (size_t)(k0 + row) * DH + c4);
            uint32_t h0, l0, h1, l1;
            split2(v.x, v.y, h0, l0);
            split2(v.z, v.w, h1, l1);
            int off = row * LDQS + c4;
            *(uint2*)&dh[off] = make_uint2(h0, h1);
            *(uint2*)&dl[off] = make_uint2(l0, l1);
        }
        __syncthreads();

        if (k0 > qw0 + 15) continue;     // block fully above causal diagonal for this warp

        // ---- S = Q K^T (3-term split) ----
        float Sv[8][4];
#pragma unroll
        for (int nt = 0; nt < 8; nt++)
#pragma unroll
            for (int e = 0; e < 4; e++) Sv[nt][e] = 0.f;

#pragma unroll
        for (int ks = 0; ks < 4; ks++) {
            uint32_t ah[4], al[4];
            ldsm_x4(ah[0], ah[1], ah[2], ah[3], q_hi_base + ks * 32u);
            ldsm_x4(al[0], al[1], al[2], al[3], q_lo_base + ks * 32u);
#pragma unroll
            for (int nt = 0; nt < 8; nt++) {
                uint32_t koff = (uint32_t)(nt * 8 * LDQS + ks * 16) * 2u;
                uint32_t bh0, bh1, bl0, bl1;
                ldsm_x2(bh0, bh1, k_hi_base + koff);
                ldsm_x2(bl0, bl1, k_lo_base + koff);
                mma16816(Sv[nt], ah, bh0, bh1);
                mma16816(Sv[nt], ah, bl0, bl1);
                mma16816(Sv[nt], al, bh0, bh1);
            }
        }

        // ---- causal mask (only needed near diagonal) ----
        if (k0 + 63 > qw0) {
#pragma unroll
            for (int nt = 0; nt < 8; nt++)
#pragma unroll
                for (int e = 0; e < 4; e++) {
                    int key = k0 + nt * 8 + (lane & 3) * 2 + (e & 1);
                    int row = qw0 + (lane >> 2) + (e >> 1) * 8;
                    if (key > row) Sv[nt][e] = -1e30f;
                }
        }

        // ---- online softmax (exp2 domain), rescale O ----
#pragma unroll
        for (int h2 = 0; h2 < 2; h2++) {
            float mx = -1e30f;
#pragma unroll
            for (int nt = 0; nt < 8; nt++)
                mx = fmaxf(mx, fmaxf(Sv[nt][h2 * 2], Sv[nt][h2 * 2 + 1]));
            mx = fmaxf(mx, __shfl_xor_sync(0xffffffffu, mx, 1));
            mx = fmaxf(mx, __shfl_xor_sync(0xffffffffu, mx, 2));
            float mnew = fmaxf(mrow[h2], mx);
            float corr = exp2f(mrow[h2] - mnew);
            mrow[h2] = mnew;

            float ls = 0.f;
#pragma unroll
            for (int nt = 0; nt < 8; nt++) {
                float p0 = exp2f(Sv[nt][h2 * 2]     - mnew);
                float p1 = exp2f(Sv[nt][h2 * 2 + 1] - mnew);
                Sv[nt][h2 * 2]     = p0;
                Sv[nt][h2 * 2 + 1] = p1;
                ls += p0 + p1;
            }
            ls += __shfl_xor_sync(0xffffffffu, ls, 1);
            ls += __shfl_xor_sync(0xffffffffu, ls, 2);
            lrow[h2] = lrow[h2] * corr + ls;
#pragma unroll
            for (int nt = 0; nt < 8; nt++) {
                Ov[nt][h2 * 2]     *= corr;
                Ov[nt][h2 * 2 + 1] *= corr;
            }
        }

        // ---- O += P V (3-term split; P accumulator layout == A fragment) ----
#pragma unroll
        for (int ks = 0; ks < 4; ks++) {
            uint32_t ph[4], pl[4];
            split2(Sv[2 * ks][0],     Sv[2 * ks][1],     ph[0], pl[0]);
            split2(Sv[2 * ks][2],     Sv[2 * ks][3],     ph[1], pl[1]);
            split2(Sv[2 * ks + 1][0], Sv[2 * ks + 1][1], ph[2], pl[2]);
            split2(Sv[2 * ks + 1][2], Sv[2 * ks + 1][3], ph[3], pl[3]);
#pragma unroll
            for (int nt = 0; nt < 8; nt++) {
                uint32_t voff = (uint32_t)(ks * 16 * LDQS + nt * 8) * 2u;
                uint32_t vh0, vh1, vl0, vl1;
                ldsm_x2_trans(vh0, vh1, v_hi_base + voff);
                ldsm_x2_trans(vl0, vl1, v_lo_base + voff);
                mma16816(Ov[nt], ph, vh0, vh1);
                mma16816(Ov[nt], ph, vl0, vl1);
                mma16816(Ov[nt], pl, vh0, vh1);
            }
        }
    }

    // ---- epilogue: y[b][t][h*64+d] = O / l ----
    const int b = bh >> 4;
    const int h = bh & 15;
    float inv0 = 1.f / lrow[0];
    float inv1 = 1.f / lrow[1];
#pragma unroll
    for (int h2 = 0; h2 < 2; h2++) {
        float inv = h2 ? inv1 : inv0;
        size_t t = (size_t)qw0 + (lane >> 2) + h2 * 8;
        float* dst = g_Y + ((size_t)b * T_SEQ + t) * NDIM + h * DH + (lane & 3) * 2;
#pragma unroll
        for (int nt = 0; nt < 8; nt++) {
            float2 v = make_float2(Ov[nt][h2 * 2] * inv, Ov[nt][h2 * 2 + 1] * inv);
            *(float2*)(dst + nt * 8) = v;
        }
    }
}

// ---------------------------------------------------------------------------
extern "C" void kernel_launch(void* const* d_in, const int* in_sizes, int n_in,
                              void* d_out, int out_size)
{
    (void)in_sizes; (void)n_in; (void)out_size;
    const float* x      = (const float*)d_in[0];   // [4,2048,1024]
    const float* W_attn = (const float*)d_in[1];   // [1024,3072]
    const float* b_attn = (const float*)d_in[2];   // [3072]
    const float* W_proj = (const float*)d_in[3];   // [1024,1024]
    const float* b_proj = (const float*)d_in[4];   // [1024]
    float* out = (float*)d_out;                    // [4,2048,1024]

    cudaFuncSetAttribute(attn_mma_kernel,
                         cudaFuncAttributeMaxDynamicSharedMemorySize, ATTN_SMEM);

    // 1) QKV GEMM (tensor cores, bf16 split) + scatter to [bh][t][d]
    mma_gemm<3072, 0><<<dim3(3072 / 128, M_ROWS / 128), 256>>>(
        x, W_attn, b_attn, nullptr);

    // 2) Causal flash attention (tensor cores, bf16 split)
    attn_mma_kernel<<<dim3(T_SEQ / 128, BH_TOT), 256, ATTN_SMEM>>>();

    // 3) Output projection (tensor cores, bf16 split)
    mma_gemm<1024, 1><<<dim3(1024 / 128, M_ROWS / 128), 256>>>(
        nullptr, W_proj, b_proj, out);
}

// round 15
// speedup vs baseline: 2.1427x; 1.2087x over previous
#include <cuda_runtime.h>
#include <cuda_bf16.h>
#include <cstdint>

// Problem shape (fixed by reference): B=4, T=2048, N=1024, H=16, Dh=64
#define B_SZ   4
#define T_SEQ  2048
#define NDIM   1024
#define NH     16
#define DH     64
#define BH_TOT (B_SZ * NH)          // 64
#define M_ROWS (B_SZ * T_SEQ)       // 8192
#define K_DIM  1024
#define QKV_N  3072

#define QS (0.125f * 1.4426950408889634f)   // 1/sqrt(Dh) * log2(e), folded into Q

// Scratch (device globals — allocation-free per harness rules).
#define QKV_ELEMS ((size_t)BH_TOT * T_SEQ * DH)
__device__ __nv_bfloat16 g_Qh[QKV_ELEMS], g_Ql[QKV_ELEMS];
__device__ __nv_bfloat16 g_Kh[QKV_ELEMS], g_Kl[QKV_ELEMS];
__device__ __nv_bfloat16 g_Vh[QKV_ELEMS], g_Vl[QKV_ELEMS];
__device__ __nv_bfloat16 g_Yh[(size_t)M_ROWS * NDIM], g_Yl[(size_t)M_ROWS * NDIM];
__device__ __nv_bfloat16 g_xh[(size_t)M_ROWS * K_DIM], g_xl[(size_t)M_ROWS * K_DIM];
__device__ __nv_bfloat16 g_Wah[(size_t)K_DIM * QKV_N], g_Wal[(size_t)K_DIM * QKV_N];
__device__ __nv_bfloat16 g_Wph[(size_t)K_DIM * NDIM],  g_Wpl[(size_t)K_DIM * NDIM];

// ---------------------------------------------------------------------------
// PTX helpers
// ---------------------------------------------------------------------------
__device__ __forceinline__ uint32_t smem_u32(const void* p) {
    return (uint32_t)__cvta_generic_to_shared(p);
}
__device__ __forceinline__ void ldsm_x4(uint32_t& r0, uint32_t& r1,
                                        uint32_t& r2, uint32_t& r3, uint32_t addr) {
    asm volatile("ldmatrix.sync.aligned.m8n8.x4.shared.b16 {%0,%1,%2,%3}, [%4];"
                 : "=r"(r0), "=r"(r1), "=r"(r2), "=r"(r3) : "r"(addr));
}
__device__ __forceinline__ void ldsm_x2(uint32_t& r0, uint32_t& r1, uint32_t addr) {
    asm volatile("ldmatrix.sync.aligned.m8n8.x2.shared.b16 {%0,%1}, [%2];"
                 : "=r"(r0), "=r"(r1) : "r"(addr));
}
__device__ __forceinline__ void ldsm_x2_trans(uint32_t& r0, uint32_t& r1, uint32_t addr) {
    asm volatile("ldmatrix.sync.aligned.m8n8.x2.trans.shared.b16 {%0,%1}, [%2];"
                 : "=r"(r0), "=r"(r1) : "r"(addr));
}
__device__ __forceinline__ void mma16816(float* c, const uint32_t* a,
                                         uint32_t b0, uint32_t b1) {
    asm volatile(
        "mma.sync.aligned.m16n8k16.row.col.f32.bf16.bf16.f32 "
        "{%0,%1,%2,%3}, {%4,%5,%6,%7}, {%8,%9}, {%0,%1,%2,%3};"
        : "+f"(c[0]), "+f"(c[1]), "+f"(c[2]), "+f"(c[3])
        : "r"(a[0]), "r"(a[1]), "r"(a[2]), "r"(a[3]), "r"(b0), "r"(b1));
}
__device__ __forceinline__ void cp_async16(uint32_t smem_addr, const void* gptr) {
    asm volatile("cp.async.cg.shared.global [%0], [%1], 16;"
                 :: "r"(smem_addr), "l"(gptr));
}
__device__ __forceinline__ void cp_commit() {
    asm volatile("cp.async.commit_group;");
}
template <int NW>
__device__ __forceinline__ void cp_wait() {
    asm volatile("cp.async.wait_group %0;" :: "n"(NW));
}

// fp32 pair -> (hi bf16x2, lo bf16x2), lo = residual
__device__ __forceinline__ void split2(float x, float y, uint32_t& hi, uint32_t& lo) {
    __nv_bfloat16 hx = __float2bfloat16(x);
    __nv_bfloat16 hy = __float2bfloat16(y);
    __nv_bfloat162 h; h.x = hx; h.y = hy;
    __nv_bfloat162 l = __floats2bfloat162_rn(x - __bfloat162float(hx),
                                             y - __bfloat162float(hy));
    hi = *reinterpret_cast<uint32_t*>(&h);
    lo = *reinterpret_cast<uint32_t*>(&l);
}

// ---------------------------------------------------------------------------
// One-shot split kernels: fp32 -> bf16 hi/lo. SEL: 0=x, 1=W_attn, 2=W_proj
// ---------------------------------------------------------------------------
template <int SEL>
__global__ void split_src(const float* __restrict__ s, int n4)
{
    __nv_bfloat16* h = (SEL == 0) ? g_xh : (SEL == 1) ? g_Wah : g_Wph;
    __nv_bfloat16* l = (SEL == 0) ? g_xl : (SEL == 1) ? g_Wal : g_Wpl;
    int i = blockIdx.x * blockDim.x + threadIdx.x;
    if (i < n4) {
        float4 v = ((const float4*)s)[i];
        uint32_t h0, l0, h1, l1;
        split2(v.x, v.y, h0, l0);
        split2(v.z, v.w, h1, l1);
        ((uint2*)h)[i] = make_uint2(h0, h1);
        ((uint2*)l)[i] = make_uint2(l0, l1);
    }
}

// ---------------------------------------------------------------------------
// Tensor-core GEMM, pre-split bf16 hi/lo inputs, 2-stage cp.async pipeline.
// C[8192, N] = A[8192,1024] @ W[1024,N] + bias
// MODE 0: A=g_x*, W=g_Wa*, epilogue scatters split bf16 into g_Q/g_K/g_V
// MODE 1: A=g_Y*, W=g_Wp*, epilogue writes fp32 Cout
// CTA tile 128x128, BK=32, 256 threads (8 warps, 64x32 each).
// ---------------------------------------------------------------------------
#define LDA 40     // halves per A smem row (32 + 8 pad)
#define LDB 136    // halves per B smem row (128 + 8 pad)
#define A_REG (128 * LDA)            // 5120 halves per A array
#define B_REG (32 * LDB)             // 4352 halves per B array
#define STAGE_H (2 * A_REG + 2 * B_REG)   // 18944 halves
#define GEMM_SMEM (2 * STAGE_H * 2)       // 75776 bytes

__device__ __forceinline__ void store_qkv_pair(int r, int c, float v0, float v1) {
    int b = r >> 11;
    int t = r & 2047;
    int which = c >> 10;           // 0=Q 1=K 2=V
    int n = c & 1023;
    int h = n >> 6;
    int d = n & 63;                // even
    if (which == 0) { v0 *= QS; v1 *= QS; }
    uint32_t hi, lo;
    split2(v0, v1, hi, lo);
    __nv_bfloat16* dh = (which == 0) ? g_Qh : (which == 1) ? g_Kh : g_Vh;
    __nv_bfloat16* dl = (which == 0) ? g_Ql : (which == 1) ? g_Kl : g_Vl;
    size_t idx = (((size_t)(b * NH + h) * T_SEQ) + t) * DH + d;
    *(uint32_t*)&dh[idx] = hi;
    *(uint32_t*)&dl[idx] = lo;
}

template <int N, int MODE>
__global__ __launch_bounds__(256, 2)
void mma_gemm(const float* __restrict__ bias, float* __restrict__ Cout)
{
    extern __shared__ __align__(16) __nv_bfloat16 gsm[];

    const __nv_bfloat16* Ah_g = (MODE == 0) ? g_xh : g_Yh;
    const __nv_bfloat16* Al_g = (MODE == 0) ? g_xl : g_Yl;
    const __nv_bfloat16* Bh_g = (MODE == 0) ? g_Wah : g_Wph;
    const __nv_bfloat16* Bl_g = (MODE == 0) ? g_Wal : g_Wpl;

    const int tid  = threadIdx.x;
    const int lane = tid & 31;
    const int warp = tid >> 5;
    const int wm   = warp & 1;
    const int wn   = warp >> 1;
    const int row0 = blockIdx.y * 128;
    const int col0 = blockIdx.x * 128;

    const uint32_t smem_base = smem_u32(gsm);

    float acc[4][4][4];
#pragma unroll
    for (int mt = 0; mt < 4; mt++)
#pragma unroll
        for (int nt = 0; nt < 4; nt++)
#pragma unroll
            for (int e = 0; e < 4; e++) acc[mt][nt][e] = 0.f;

    // fill mapping: A chunks (512 of 16B per array), B chunks (512 per array)
    const int ach_row = tid >> 1;                 // chunk c=tid,tid+256 -> rows tid>>1 pattern below
    // (computed inline per chunk)

    // ldmatrix per-thread offsets (halves, within a stage)
    const int a_off = (wm * 64 + (lane & 15)) * LDA + ((lane >> 4) << 3);
    const int b_off = (lane & 15) * LDB + wn * 32;

    const int NK = K_DIM / 32;

    // ---- fill helper (as lambda) ----
    auto fill = [&](int stage, int k0) {
        uint32_t sb = smem_base + (uint32_t)(stage * STAGE_H) * 2u;
#pragma unroll
        for (int j = 0; j < 2; j++) {
            int c = tid + j * 256;               // 0..511
            int row = c >> 2;                    // 0..127
            int col8 = (c & 3) * 8;              // halves
            uint32_t doff = (uint32_t)(row * LDA + col8) * 2u;
            const __nv_bfloat16* sh = Ah_g + (size_t)(row0 + row) * K_DIM + k0 + col8;
            const __nv_bfloat16* sl = Al_g + (size_t)(row0 + row) * K_DIM + k0 + col8;
            cp_async16(sb + doff, sh);
            cp_async16(sb + (uint32_t)A_REG * 2u + doff, sl);
        }
#pragma unroll
        for (int j = 0; j < 2; j++) {
            int c = tid + j * 256;               // 0..511
            int row = c >> 4;                    // 0..31
            int col8 = (c & 15) * 8;
            uint32_t doff = (uint32_t)(row * LDB + col8) * 2u;
            const __nv_bfloat16* sh = Bh_g + (size_t)(k0 + row) * N + col0 + col8;
            const __nv_bfloat16* sl = Bl_g + (size_t)(k0 + row) * N + col0 + col8;
            cp_async16(sb + (uint32_t)(2 * A_REG) * 2u + doff, sh);
            cp_async16(sb + (uint32_t)(2 * A_REG + B_REG) * 2u + doff, sl);
        }
    };

    fill(0, 0);
    cp_commit();

#pragma unroll 1
    for (int i = 0; i < NK; i++) {
        if (i + 1 < NK) { fill((i + 1) & 1, (i + 1) * 32); cp_commit(); }
        if (i + 1 < NK) cp_wait<1>(); else cp_wait<0>();
        __syncthreads();

        uint32_t sb = smem_base + (uint32_t)((i & 1) * STAGE_H) * 2u;
        uint32_t a_hi_base = sb + (uint32_t)a_off * 2u;
        uint32_t a_lo_base = a_hi_base + (uint32_t)A_REG * 2u;
        uint32_t b_hi_base = sb + (uint32_t)(2 * A_REG + b_off) * 2u;
        uint32_t b_lo_base = b_hi_base + (uint32_t)B_REG * 2u;

#pragma unroll
        for (int ks = 0; ks < 2; ks++) {
            uint32_t bh[4][2], bl[4][2];
#pragma unroll
            for (int nt = 0; nt < 4; nt++) {
                uint32_t boff = (uint32_t)((ks * 16) * LDB + nt * 8) * 2u;
                ldsm_x2_trans(bh[nt][0], bh[nt][1], b_hi_base + boff);
                ldsm_x2_trans(bl[nt][0], bl[nt][1], b_lo_base + boff);
            }
#pragma unroll
            for (int mt = 0; mt < 4; mt++) {
                uint32_t ah[4], al[4];
                uint32_t aoff = (uint32_t)(mt * 16 * LDA + ks * 16) * 2u;
                ldsm_x4(ah[0], ah[1], ah[2], ah[3], a_hi_base + aoff);
                ldsm_x4(al[0], al[1], al[2], al[3], a_lo_base + aoff);
#pragma unroll
                for (int nt = 0; nt < 4; nt++) {
                    mma16816(acc[mt][nt], ah, bh[nt][0], bh[nt][1]);
                    mma16816(acc[mt][nt], ah, bl[nt][0], bl[nt][1]);
                    mma16816(acc[mt][nt], al, bh[nt][0], bh[nt][1]);
                }
            }
        }
        __syncthreads();
    }

    // ---- epilogue ----
    const int r_lane = lane >> 2;
    const int c_lane = (lane & 3) * 2;
#pragma unroll
    for (int mt = 0; mt < 4; mt++) {
#pragma unroll
        for (int nt = 0; nt < 4; nt++) {
            int c = col0 + wn * 32 + nt * 8 + c_lane;
            float b0 = bias[c], b1 = bias[c + 1];
#pragma unroll
            for (int h2 = 0; h2 < 2; h2++) {
                int r = row0 + wm * 64 + mt * 16 + r_lane + h2 * 8;
                float v0 = acc[mt][nt][h2 * 2 + 0] + b0;
                float v1 = acc[mt][nt][h2 * 2 + 1] + b1;
                if (MODE == 0) {
                    store_qkv_pair(r, c, v0, v1);
                } else {
                    *(float2*)&Cout[(size_t)r * N + c] = make_float2(v0, v1);
                }
            }
        }
    }
}

// ---------------------------------------------------------------------------
// Tensor-core causal flash attention, pre-split bf16 hi/lo Q/K/V.
// CTA = 128 queries x one (b,h). 8 warps x 16 query rows. 64-key blocks.
// Softmax in exp2 domain (log2e + 1/sqrt(Dh) already folded into Q).
// ---------------------------------------------------------------------------
#define LDQS 72
#define Q_HALVES (128 * LDQS)
#define KV_HALVES (64 * LDQS)
#define ATTN_SMEM ((2 * Q_HALVES + 4 * KV_HALVES) * 2)   // 73728 bytes

__global__ __launch_bounds__(256, 2)
void attn_mma_kernel()
{
    extern __shared__ __align__(16) __nv_bfloat16 sm[];
    __nv_bfloat16* Qh = sm;
    __nv_bfloat16* Ql = Qh + Q_HALVES;
    __nv_bfloat16* Kh = Ql + Q_HALVES;
    __nv_bfloat16* Kl = Kh + KV_HALVES;
    __nv_bfloat16* Vh = Kl + KV_HALVES;
    __nv_bfloat16* Vl = Vh + KV_HALVES;

    const int tid  = threadIdx.x;
    const int lane = tid & 31;
    const int warp = tid >> 5;
    const int qt   = blockIdx.x;
    const int bh   = blockIdx.y;
    const int q0   = qt * 128;
    const int qw0  = q0 + warp * 16;

    const __nv_bfloat16* Qhg = g_Qh + (size_t)bh * T_SEQ * DH;
    const __nv_bfloat16* Qlg = g_Ql + (size_t)bh * T_SEQ * DH;
    const __nv_bfloat16* Khg = g_Kh + (size_t)bh * T_SEQ * DH;
    const __nv_bfloat16* Klg = g_Kl + (size_t)bh * T_SEQ * DH;
    const __nv_bfloat16* Vhg = g_Vh + (size_t)bh * T_SEQ * DH;
    const __nv_bfloat16* Vlg = g_Vl + (size_t)bh * T_SEQ * DH;

    // ---- load Q tile (pure copy, already scaled+split) ----
#pragma unroll
    for (int it = 0; it < 8; it++) {
        int s = tid + it * 256;              // 0..2047 uint4 slots
        int arr = s >> 10;                   // 0=hi 1=lo
        int w = s & 1023;
        int row = w >> 3;
        int c8  = (w & 7) * 8;
        const __nv_bfloat16* src = (arr ? Qlg : Qhg) + (size_t)(q0 + row) * DH + c8;
        __nv_bfloat16* dst = (arr ? Ql : Qh) + row * LDQS + c8;
        *(uint4*)dst = *(const uint4*)src;
    }

    const uint32_t q_hi_base = smem_u32(&Qh[(warp * 16 + (lane & 15)) * LDQS + ((lane >> 4) << 3)]);
    const uint32_t q_lo_base = smem_u32(&Ql[(warp * 16 + (lane & 15)) * LDQS + ((lane >> 4) << 3)]);
    const uint32_t k_hi_base = smem_u32(&Kh[(lane & 7) * LDQS + (((lane >> 3) & 1) << 3)]);
    const uint32_t k_lo_base = smem_u32(&Kl[(lane & 7) * LDQS + (((lane >> 3) & 1) << 3)]);
    const uint32_t v_hi_base = smem_u32(&Vh[(lane & 15) * LDQS]);
    const uint32_t v_lo_base = smem_u32(&Vl[(lane & 15) * LDQS]);

    float Ov[8][4];
#pragma unroll
    for (int nt = 0; nt < 8; nt++)
#pragma unroll
        for (int e = 0; e < 4; e++) Ov[nt][e] = 0.f;
    float mrow[2] = {-1e30f, -1e30f};
    float lrow[2] = {0.f, 0.f};

    const int nkb = 2 * (qt + 1);

    for (int jb = 0; jb < nkb; jb++) {
        const int k0 = jb * 64;
        __syncthreads();
        // ---- load K,V block (pure copy) ----
#pragma unroll
        for (int it = 0; it < 8; it++) {
            int s = tid + it * 256;          // 0..2047
            int arr = s >> 9;                // 0=Kh 1=Kl 2=Vh 3=Vl
            int w = s & 511;
            int row = w >> 3;
            int c8  = (w & 7) * 8;
            const __nv_bfloat16* src =
                ((arr == 0) ? Khg : (arr == 1) ? Klg : (arr == 2) ? Vhg : Vlg)
                + (size_t)(k0 + row) * DH + c8;
            __nv_bfloat16* dst =
                ((arr == 0) ? Kh : (arr == 1) ? Kl : (arr == 2) ? Vh : Vl)
                + row * LDQS + c8;
            *(uint4*)dst = *(const uint4*)src;
        }
        __syncthreads();

        if (k0 > qw0 + 15) continue;

        // ---- S = Q K^T (3-term split) ----
        float Sv[8][4];
#pragma unroll
        for (int nt = 0; nt < 8; nt++)
#pragma unroll
            for (int e = 0; e < 4; e++) Sv[nt][e] = 0.f;

#pragma unroll
        for (int ks = 0; ks < 4; ks++) {
            uint32_t ah[4], al[4];
            ldsm_x4(ah[0], ah[1], ah[2], ah[3], q_hi_base + ks * 32u);
            ldsm_x4(al[0], al[1], al[2], al[3], q_lo_base + ks * 32u);
#pragma unroll
            for (int nt = 0; nt < 8; nt++) {
                uint32_t koff = (uint32_t)(nt * 8 * LDQS + ks * 16) * 2u;
                uint32_t bh0, bh1, bl0, bl1;
                ldsm_x2(bh0, bh1, k_hi_base + koff);
                ldsm_x2(bl0, bl1, k_lo_base + koff);
                mma16816(Sv[nt], ah, bh0, bh1);
                mma16816(Sv[nt], ah, bl0, bl1);
                mma16816(Sv[nt], al, bh0, bh1);
            }
        }

        // ---- causal mask ----
        if (k0 + 63 > qw0) {
#pragma unroll
            for (int nt = 0; nt < 8; nt++)
#pragma unroll
                for (int e = 0; e < 4; e++) {
                    int key = k0 + nt * 8 + (lane & 3) * 2 + (e & 1);
                    int row = qw0 + (lane >> 2) + (e >> 1) * 8;
                    if (key > row) Sv[nt][e] = -1e30f;
                }
        }

        // ---- online softmax (exp2 domain) ----
#pragma unroll
        for (int h2 = 0; h2 < 2; h2++) {
            float mx = -1e30f;
#pragma unroll
            for (int nt = 0; nt < 8; nt++)
                mx = fmaxf(mx, fmaxf(Sv[nt][h2 * 2], Sv[nt][h2 * 2 + 1]));
            mx = fmaxf(mx, __shfl_xor_sync(0xffffffffu, mx, 1));
            mx = fmaxf(mx, __shfl_xor_sync(0xffffffffu, mx, 2));
            float mnew = fmaxf(mrow[h2], mx);
            float corr = exp2f(mrow[h2] - mnew);
            mrow[h2] = mnew;

            float ls = 0.f;
#pragma unroll
            for (int nt = 0; nt < 8; nt++) {
                float p0 = exp2f(Sv[nt][h2 * 2]     - mnew);
                float p1 = exp2f(Sv[nt][h2 * 2 + 1] - mnew);
                Sv[nt][h2 * 2]     = p0;
                Sv[nt][h2 * 2 + 1] = p1;
                ls += p0 + p1;
            }
            ls += __shfl_xor_sync(0xffffffffu, ls, 1);
            ls += __shfl_xor_sync(0xffffffffu, ls, 2);
            lrow[h2] = lrow[h2] * corr + ls;
#pragma unroll
            for (int nt = 0; nt < 8; nt++) {
                Ov[nt][h2 * 2]     *= corr;
                Ov[nt][h2 * 2 + 1] *= corr;
            }
        }

        // ---- O += P V (3-term split) ----
#pragma unroll
        for (int ks = 0; ks < 4; ks++) {
            uint32_t ph[4], pl[4];
            split2(Sv[2 * ks][0],     Sv[2 * ks][1],     ph[0], pl[0]);
            split2(Sv[2 * ks][2],     Sv[2 * ks][3],     ph[1], pl[1]);
            split2(Sv[2 * ks + 1][0], Sv[2 * ks + 1][1], ph[2], pl[2]);
            split2(Sv[2 * ks + 1][2], Sv[2 * ks + 1][3], ph[3], pl[3]);
#pragma unroll
            for (int nt = 0; nt < 8; nt++) {
                uint32_t voff = (uint32_t)(ks * 16 * LDQS + nt * 8) * 2u;
                uint32_t vh0, vh1, vl0, vl1;
                ldsm_x2_trans(vh0, vh1, v_hi_base + voff);
                ldsm_x2_trans(vl0, vl1, v_lo_base + voff);
                mma16816(Ov[nt], ph, vh0, vh1);
                mma16816(Ov[nt], ph, vl0, vl1);
                mma16816(Ov[nt], pl, vh0, vh1);
            }
        }
    }

    // ---- epilogue: Y = O / l, written pre-split for the proj GEMM ----
    const int b = bh >> 4;
    const int h = bh & 15;
    float inv0 = 1.f / lrow[0];
    float inv1 = 1.f / lrow[1];
#pragma unroll
    for (int h2 = 0; h2 < 2; h2++) {
        float inv = h2 ? inv1 : inv0;
        size_t t = (size_t)qw0 + (lane >> 2) + h2 * 8;
        size_t base = ((size_t)b * T_SEQ + t) * NDIM + h * DH + (lane & 3) * 2;
#pragma unroll
        for (int nt = 0; nt < 8; nt++) {
            uint32_t hi, lo;
            split2(Ov[nt][h2 * 2] * inv, Ov[nt][h2 * 2 + 1] * inv, hi, lo);
            *(uint32_t*)&g_Yh[base + nt * 8] = hi;
            *(uint32_t*)&g_Yl[base + nt * 8] = lo;
        }
    }
}

// ---------------------------------------------------------------------------
extern "C" void kernel_launch(void* const* d_in, const int* in_sizes, int n_in,
                              void* d_out, int out_size)
{
    (void)in_sizes; (void)n_in; (void)out_size;
    const float* x      = (const float*)d_in[0];   // [4,2048,1024]
    const float* W_attn = (const float*)d_in[1];   // [1024,3072]
    const float* b_attn = (const float*)d_in[2];   // [3072]
    const float* W_proj = (const float*)d_in[3];   // [1024,1024]
    const float* b_proj = (const float*)d_in[4];   // [1024]
    float* out = (float*)d_out;                    // [4,2048,1024]

    cudaFuncSetAttribute(attn_mma_kernel,
                         cudaFuncAttributeMaxDynamicSharedMemorySize, ATTN_SMEM);
    cudaFuncSetAttribute(mma_gemm<QKV_N, 0>,
                         cudaFuncAttributeMaxDynamicSharedMemorySize, GEMM_SMEM);
    cudaFuncSetAttribute(mma_gemm<NDIM, 1>,
                         cudaFuncAttributeMaxDynamicSharedMemorySize, GEMM_SMEM);

    // 0) one-shot fp32 -> bf16 hi/lo splits
    split_src<0><<<(M_ROWS * K_DIM / 4 + 255) / 256, 256>>>(x,      M_ROWS * K_DIM / 4);
    split_src<1><<<(K_DIM * QKV_N / 4 + 255) / 256, 256>>>(W_attn, K_DIM * QKV_N / 4);
    split_src<2><<<(K_DIM * NDIM / 4 + 255) / 256, 256>>>(W_proj, K_DIM * NDIM / 4);

    // 1) QKV GEMM (pipelined) + split-scatter to g_Q/g_K/g_V
    mma_gemm<QKV_N, 0><<<dim3(QKV_N / 128, M_ROWS / 128), 256, GEMM_SMEM>>>(
        b_attn, nullptr);

    // 2) Causal flash attention (tensor cores), writes split Y
    attn_mma_kernel<<<dim3(T_SEQ / 128, BH_TOT), 256, ATTN_SMEM>>>();

    // 3) Output projection (pipelined)
    mma_gemm<NDIM, 1><<<dim3(NDIM / 128, M_ROWS / 128), 256, GEMM_SMEM>>>(
        b_proj, out);
}

// round 17
// speedup vs baseline: 2.3375x; 1.0909x over previous
#include <cuda_runtime.h>
#include <cuda_bf16.h>
#include <cstdint>

// Problem shape (fixed by reference): B=4, T=2048, N=1024, H=16, Dh=64
#define B_SZ   4
#define T_SEQ  2048
#define NDIM   1024
#define NH     16
#define DH     64
#define BH_TOT (B_SZ * NH)          // 64
#define M_ROWS (B_SZ * T_SEQ)       // 8192
#define K_DIM  1024
#define QKV_N  3072

#define QS (0.125f * 1.4426950408889634f)   // 1/sqrt(Dh) * log2(e), folded into Q

// Scratch (device globals — allocation-free per harness rules).
#define QKV_ELEMS ((size_t)BH_TOT * T_SEQ * DH)
__device__ __nv_bfloat16 g_Qh[QKV_ELEMS], g_Ql[QKV_ELEMS];
__device__ __nv_bfloat16 g_Kh[QKV_ELEMS], g_Kl[QKV_ELEMS];
__device__ __nv_bfloat16 g_Vh[QKV_ELEMS], g_Vl[QKV_ELEMS];
__device__ __nv_bfloat16 g_Yh[(size_t)M_ROWS * NDIM], g_Yl[(size_t)M_ROWS * NDIM];
__device__ __nv_bfloat16 g_xh[(size_t)M_ROWS * K_DIM], g_xl[(size_t)M_ROWS * K_DIM];
__device__ __nv_bfloat16 g_Wah[(size_t)K_DIM * QKV_N], g_Wal[(size_t)K_DIM * QKV_N];
__device__ __nv_bfloat16 g_Wph[(size_t)K_DIM * NDIM],  g_Wpl[(size_t)K_DIM * NDIM];

// ---------------------------------------------------------------------------
// PTX helpers
// ---------------------------------------------------------------------------
__device__ __forceinline__ uint32_t smem_u32(const void* p) {
    return (uint32_t)__cvta_generic_to_shared(p);
}
__device__ __forceinline__ void ldsm_x4(uint32_t& r0, uint32_t& r1,
                                        uint32_t& r2, uint32_t& r3, uint32_t addr) {
    asm volatile("ldmatrix.sync.aligned.m8n8.x4.shared.b16 {%0,%1,%2,%3}, [%4];"
                 : "=r"(r0), "=r"(r1), "=r"(r2), "=r"(r3) : "r"(addr));
}
__device__ __forceinline__ void ldsm_x2(uint32_t& r0, uint32_t& r1, uint32_t addr) {
    asm volatile("ldmatrix.sync.aligned.m8n8.x2.shared.b16 {%0,%1}, [%2];"
                 : "=r"(r0), "=r"(r1) : "r"(addr));
}
__device__ __forceinline__ void ldsm_x2_trans(uint32_t& r0, uint32_t& r1, uint32_t addr) {
    asm volatile("ldmatrix.sync.aligned.m8n8.x2.trans.shared.b16 {%0,%1}, [%2];"
                 : "=r"(r0), "=r"(r1) : "r"(addr));
}
__device__ __forceinline__ void mma16816(float* c, const uint32_t* a,
                                         uint32_t b0, uint32_t b1) {
    asm volatile(
        "mma.sync.aligned.m16n8k16.row.col.f32.bf16.bf16.f32 "
        "{%0,%1,%2,%3}, {%4,%5,%6,%7}, {%8,%9}, {%0,%1,%2,%3};"
        : "+f"(c[0]), "+f"(c[1]), "+f"(c[2]), "+f"(c[3])
        : "r"(a[0]), "r"(a[1]), "r"(a[2]), "r"(a[3]), "r"(b0), "r"(b1));
}
__device__ __forceinline__ void cp_async16(uint32_t smem_addr, const void* gptr) {
    asm volatile("cp.async.cg.shared.global [%0], [%1], 16;"
                 :: "r"(smem_addr), "l"(gptr));
}
__device__ __forceinline__ void cp_commit() {
    asm volatile("cp.async.commit_group;");
}
template <int NW>
__device__ __forceinline__ void cp_wait() {
    asm volatile("cp.async.wait_group %0;" :: "n"(NW));
}

// fp32 pair -> (hi bf16x2, lo bf16x2), lo = residual
__device__ __forceinline__ void split2(float x, float y, uint32_t& hi, uint32_t& lo) {
    __nv_bfloat16 hx = __float2bfloat16(x);
    __nv_bfloat16 hy = __float2bfloat16(y);
    __nv_bfloat162 h; h.x = hx; h.y = hy;
    __nv_bfloat162 l = __floats2bfloat162_rn(x - __bfloat162float(hx),
                                             y - __bfloat162float(hy));
    hi = *reinterpret_cast<uint32_t*>(&h);
    lo = *reinterpret_cast<uint32_t*>(&l);
}

// ---------------------------------------------------------------------------
// One-shot split kernels: fp32 -> bf16 hi/lo. SEL: 0=x, 1=W_attn, 2=W_proj
// ---------------------------------------------------------------------------
template <int SEL>
__global__ void split_src(const float* __restrict__ s, int n4)
{
    __nv_bfloat16* h = (SEL == 0) ? g_xh : (SEL == 1) ? g_Wah : g_Wph;
    __nv_bfloat16* l = (SEL == 0) ? g_xl : (SEL == 1) ? g_Wal : g_Wpl;
    int i = blockIdx.x * blockDim.x + threadIdx.x;
    if (i < n4) {
        float4 v = ((const float4*)s)[i];
        uint32_t h0, l0, h1, l1;
        split2(v.x, v.y, h0, l0);
        split2(v.z, v.w, h1, l1);
        ((uint2*)h)[i] = make_uint2(h0, h1);
        ((uint2*)l)[i] = make_uint2(l0, l1);
    }
}

// ---------------------------------------------------------------------------
// Tensor-core GEMM, pre-split bf16 hi/lo inputs, 3-stage cp.async pipeline,
// ONE barrier per k-iteration (fill after MMA cannot clobber a stage in use:
// the barrier proves all warps finished stage i-1, and fill targets (i+2)%3
// == (i-1)%3).
// C[8192, N] = A[8192,1024] @ W[1024,N] + bias
// MODE 0: A=g_x*, epilogue scatters split bf16 into g_Q/g_K/g_V
// MODE 1: A=g_Y*, epilogue writes fp32 Cout
// CTA tile 128x128, BK=32, 256 threads (8 warps, 64x32 each).
// ---------------------------------------------------------------------------
#define LDA 40     // halves per A smem row (32 + 8 pad)
#define LDB 136    // halves per B smem row (128 + 8 pad)
#define A_REG (128 * LDA)            // 5120 halves per A array
#define B_REG (32 * LDB)             // 4352 halves per B array
#define STAGE_H (2 * A_REG + 2 * B_REG)   // 18944 halves
#define GEMM_SMEM (3 * STAGE_H * 2)       // 113664 bytes

__device__ __forceinline__ void store_qkv_pair(int r, int c, float v0, float v1) {
    int b = r >> 11;
    int t = r & 2047;
    int which = c >> 10;           // 0=Q 1=K 2=V
    int n = c & 1023;
    int h = n >> 6;
    int d = n & 63;                // even
    if (which == 0) { v0 *= QS; v1 *= QS; }
    uint32_t hi, lo;
    split2(v0, v1, hi, lo);
    __nv_bfloat16* dh = (which == 0) ? g_Qh : (which == 1) ? g_Kh : g_Vh;
    __nv_bfloat16* dl = (which == 0) ? g_Ql : (which == 1) ? g_Kl : g_Vl;
    size_t idx = (((size_t)(b * NH + h) * T_SEQ) + t) * DH + d;
    *(uint32_t*)&dh[idx] = hi;
    *(uint32_t*)&dl[idx] = lo;
}

template <int N, int MODE>
__global__ __launch_bounds__(256, 2)
void mma_gemm(const float* __restrict__ bias, float* __restrict__ Cout)
{
    extern __shared__ __align__(16) __nv_bfloat16 gsm[];

    const __nv_bfloat16* Ah_g = (MODE == 0) ? g_xh : g_Yh;
    const __nv_bfloat16* Al_g = (MODE == 0) ? g_xl : g_Yl;
    const __nv_bfloat16* Bh_g = (MODE == 0) ? g_Wah : g_Wph;
    const __nv_bfloat16* Bl_g = (MODE == 0) ? g_Wal : g_Wpl;

    const int tid  = threadIdx.x;
    const int lane = tid & 31;
    const int warp = tid >> 5;
    const int wm   = warp & 1;
    const int wn   = warp >> 1;
    const int row0 = blockIdx.y * 128;
    const int col0 = blockIdx.x * 128;

    const uint32_t smem_base = smem_u32(gsm);

    float acc[4][4][4];
#pragma unroll
    for (int mt = 0; mt < 4; mt++)
#pragma unroll
        for (int nt = 0; nt < 4; nt++)
#pragma unroll
            for (int e = 0; e < 4; e++) acc[mt][nt][e] = 0.f;

    // ldmatrix per-thread offsets (halves, within a stage)
    const int a_off = (wm * 64 + (lane & 15)) * LDA + ((lane >> 4) << 3);
    const int b_off = (lane & 15) * LDB + wn * 32;

    const int NK = K_DIM / 32;

    // ---- fill one stage ----
    auto fill = [&](int stage, int k0) {
        uint32_t sb = smem_base + (uint32_t)(stage * STAGE_H) * 2u;
#pragma unroll
        for (int j = 0; j < 2; j++) {
            int c = tid + j * 256;               // 0..511
            int row = c >> 2;                    // 0..127
            int col8 = (c & 3) * 8;              // halves
            uint32_t doff = (uint32_t)(row * LDA + col8) * 2u;
            const __nv_bfloat16* sh = Ah_g + (size_t)(row0 + row) * K_DIM + k0 + col8;
            const __nv_bfloat16* sl = Al_g + (size_t)(row0 + row) * K_DIM + k0 + col8;
            cp_async16(sb + doff, sh);
            cp_async16(sb + (uint32_t)A_REG * 2u + doff, sl);
        }
#pragma unroll
        for (int j = 0; j < 2; j++) {
            int c = tid + j * 256;               // 0..511
            int row = c >> 4;                    // 0..31
            int col8 = (c & 15) * 8;
            uint32_t doff = (uint32_t)(row * LDB + col8) * 2u;
            const __nv_bfloat16* sh = Bh_g + (size_t)(k0 + row) * N + col0 + col8;
            const __nv_bfloat16* sl = Bl_g + (size_t)(k0 + row) * N + col0 + col8;
            cp_async16(sb + (uint32_t)(2 * A_REG) * 2u + doff, sh);
            cp_async16(sb + (uint32_t)(2 * A_REG + B_REG) * 2u + doff, sl);
        }
    };

    fill(0, 0);  cp_commit();
    fill(1, 32); cp_commit();

#pragma unroll 1
    for (int i = 0; i < NK; i++) {
        if (i < NK - 1) cp_wait<1>(); else cp_wait<0>();
        __syncthreads();

        uint32_t sb = smem_base + (uint32_t)((i % 3) * STAGE_H) * 2u;
        uint32_t a_hi_base = sb + (uint32_t)a_off * 2u;
        uint32_t a_lo_base = a_hi_base + (uint32_t)A_REG * 2u;
        uint32_t b_hi_base = sb + (uint32_t)(2 * A_REG + b_off) * 2u;
        uint32_t b_lo_base = b_hi_base + (uint32_t)B_REG * 2u;

#pragma unroll
        for (int ks = 0; ks < 2; ks++) {
            uint32_t bh[4][2], bl[4][2];
#pragma unroll
            for (int nt = 0; nt < 4; nt++) {
                uint32_t boff = (uint32_t)((ks * 16) * LDB + nt * 8) * 2u;
                ldsm_x2_trans(bh[nt][0], bh[nt][1], b_hi_base + boff);
                ldsm_x2_trans(bl[nt][0], bl[nt][1], b_lo_base + boff);
            }
#pragma unroll
            for (int mt = 0; mt < 4; mt++) {
                uint32_t ah[4], al[4];
                uint32_t aoff = (uint32_t)(mt * 16 * LDA + ks * 16) * 2u;
                ldsm_x4(ah[0], ah[1], ah[2], ah[3], a_hi_base + aoff);
                ldsm_x4(al[0], al[1], al[2], al[3], a_lo_base + aoff);
#pragma unroll
                for (int nt = 0; nt < 4; nt++) {
                    mma16816(acc[mt][nt], ah, bh[nt][0], bh[nt][1]);
                    mma16816(acc[mt][nt], ah, bl[nt][0], bl[nt][1]);
                    mma16816(acc[mt][nt], al, bh[nt][0], bh[nt][1]);
                }
            }
        }

        if (i + 2 < NK) { fill((i + 2) % 3, (i + 2) * 32); cp_commit(); }
    }

    // ---- epilogue ----
    const int r_lane = lane >> 2;
    const int c_lane = (lane & 3) * 2;
#pragma unroll
    for (int mt = 0; mt < 4; mt++) {
#pragma unroll
        for (int nt = 0; nt < 4; nt++) {
            int c = col0 + wn * 32 + nt * 8 + c_lane;
            float b0 = bias[c], b1 = bias[c + 1];
#pragma unroll
            for (int h2 = 0; h2 < 2; h2++) {
                int r = row0 + wm * 64 + mt * 16 + r_lane + h2 * 8;
                float v0 = acc[mt][nt][h2 * 2 + 0] + b0;
                float v1 = acc[mt][nt][h2 * 2 + 1] + b1;
                if (MODE == 0) {
                    store_qkv_pair(r, c, v0, v1);
                } else {
                    *(float2*)&Cout[(size_t)r * N + c] = make_float2(v0, v1);
                }
            }
        }
    }
}

// ---------------------------------------------------------------------------
// Tensor-core causal flash attention, pre-split bf16 hi/lo Q/K/V.
// CTA = 128 queries x one (b,h). 8 warps x 16 query rows. 64-key blocks.
// K/V double-buffered via cp.async: next block streams in under compute.
// Softmax in exp2 domain (log2e + 1/sqrt(Dh) already folded into Q).
// ---------------------------------------------------------------------------
#define LDQS 72                       // 144B rows (16B-aligned for cp.async)
#define Q_HALVES (128 * LDQS)         // 9216 per array
#define KV_ARR   (64 * LDQS)          // 4608 halves per array
#define KV_STAGE (4 * KV_ARR)         // 18432 halves per stage (Kh,Kl,Vh,Vl)
#define ATTN_SMEM ((2 * Q_HALVES + 2 * KV_STAGE) * 2)   // 110592 bytes

__global__ __launch_bounds__(256, 2)
void attn_mma_kernel()
{
    extern __shared__ __align__(16) __nv_bfloat16 sm[];
    __nv_bfloat16* Qh = sm;
    __nv_bfloat16* Ql = Qh + Q_HALVES;

    const uint32_t sbase = smem_u32(sm);
    const uint32_t kv0   = sbase + (uint32_t)(2 * Q_HALVES) * 2u;  // stage 0 bytes

    const int tid  = threadIdx.x;
    const int lane = tid & 31;
    const int warp = tid >> 5;
    const int qt   = blockIdx.x;
    const int bh   = blockIdx.y;
    const int q0   = qt * 128;
    const int qw0  = q0 + warp * 16;

    const __nv_bfloat16* Qhg = g_Qh + (size_t)bh * T_SEQ * DH;
    const __nv_bfloat16* Qlg = g_Ql + (size_t)bh * T_SEQ * DH;
    const __nv_bfloat16* Khg = g_Kh + (size_t)bh * T_SEQ * DH;
    const __nv_bfloat16* Klg = g_Kl + (size_t)bh * T_SEQ * DH;
    const __nv_bfloat16* Vhg = g_Vh + (size_t)bh * T_SEQ * DH;
    const __nv_bfloat16* Vlg = g_Vl + (size_t)bh * T_SEQ * DH;

    // ---- fill one K/V stage via cp.async (2048 x 16B chunks) ----
    auto fillKV = [&](int stage, int k0) {
        uint32_t sb = kv0 + (uint32_t)(stage * KV_STAGE) * 2u;
#pragma unroll
        for (int it = 0; it < 8; it++) {
            int c = tid + it * 256;          // 0..2047
            int arr = c >> 9;                // 0=Kh 1=Kl 2=Vh 3=Vl
            int w = c & 511;
            int row = w >> 3;                // 0..63
            int cg  = w & 7;                 // 16B unit
            const __nv_bfloat16* src =
                ((arr == 0) ? Khg : (arr == 1) ? Klg : (arr == 2) ? Vhg : Vlg)
                + (size_t)(k0 + row) * DH + cg * 8;
            uint32_t dst = sb + (uint32_t)(arr * KV_ARR + row * LDQS + cg * 8) * 2u;
            cp_async16(dst, src);
        }
    };

    // ---- load Q tile (synchronous; visible after first barrier) ----
#pragma unroll
    for (int it = 0; it < 8; it++) {
        int s = tid + it * 256;
        int arr = s >> 10;
        int w = s & 1023;
        int row = w >> 3;
        int c8  = (w & 7) * 8;
        const __nv_bfloat16* src = (arr ? Qlg : Qhg) + (size_t)(q0 + row) * DH + c8;
        __nv_bfloat16* dst = (arr ? Ql : Qh) + row * LDQS + c8;
        *(uint4*)dst = *(const uint4*)src;
    }

    fillKV(0, 0);
    cp_commit();

    const uint32_t q_hi_base = smem_u32(&Qh[(warp * 16 + (lane & 15)) * LDQS + ((lane >> 4) << 3)]);
    const uint32_t q_lo_base = smem_u32(&Ql[(warp * 16 + (lane & 15)) * LDQS + ((lane >> 4) << 3)]);
    // per-lane byte offsets within a KV stage
    const uint32_t k_loff = (uint32_t)((lane & 7) * LDQS + (((lane >> 3) & 1) << 3)) * 2u;
    const uint32_t v_loff = (uint32_t)((lane & 15) * LDQS) * 2u;

    float Ov[8][4];
#pragma unroll
    for (int nt = 0; nt < 8; nt++)
#pragma unroll
        for (int e = 0; e < 4; e++) Ov[nt][e] = 0.f;
    float mrow[2] = {-1e30f, -1e30f};
    float lrow[2] = {0.f, 0.f};

    const int nkb = 2 * (qt + 1);

#pragma unroll 1
    for (int jb = 0; jb < nkb; jb++) {
        const int k0 = jb * 64;
        cp_wait<0>();
        __syncthreads();     // stage jb&1 visible; all warps done with stage (jb-1)&1
        if (jb + 1 < nkb) { fillKV((jb + 1) & 1, (jb + 1) * 64); cp_commit(); }

        if (k0 > qw0 + 15) continue;   // fully above causal diagonal for this warp

        uint32_t sb = kv0 + (uint32_t)((jb & 1) * KV_STAGE) * 2u;
        uint32_t k_hi_base = sb + k_loff;
        uint32_t k_lo_base = k_hi_base + (uint32_t)KV_ARR * 2u;
        uint32_t v_hi_base = sb + (uint32_t)(2 * KV_ARR) * 2u + v_loff;
        uint32_t v_lo_base = v_hi_base + (uint32_t)KV_ARR * 2u;

        // ---- S = Q K^T (3-term split) ----
        float Sv[8][4];
#pragma unroll
        for (int nt = 0; nt < 8; nt++)
#pragma unroll
            for (int e = 0; e < 4; e++) Sv[nt][e] = 0.f;

#pragma unroll
        for (int ks = 0; ks < 4; ks++) {
            uint32_t ah[4], al[4];
            ldsm_x4(ah[0], ah[1], ah[2], ah[3], q_hi_base + ks * 32u);
            ldsm_x4(al[0], al[1], al[2], al[3], q_lo_base + ks * 32u);
#pragma unroll
            for (int nt = 0; nt < 8; nt++) {
                uint32_t koff = (uint32_t)(nt * 8 * LDQS + ks * 16) * 2u;
                uint32_t bh0, bh1, bl0, bl1;
                ldsm_x2(bh0, bh1, k_hi_base + koff);
                ldsm_x2(bl0, bl1, k_lo_base + koff);
                mma16816(Sv[nt], ah, bh0, bh1);
                mma16816(Sv[nt], ah, bl0, bl1);
                mma16816(Sv[nt], al, bh0, bh1);
            }
        }

        // ---- causal mask ----
        if (k0 + 63 > qw0) {
#pragma unroll
            for (int nt = 0; nt < 8; nt++)
#pragma unroll
                for (int e = 0; e < 4; e++) {
                    int key = k0 + nt * 8 + (lane & 3) * 2 + (e & 1);
                    int row = qw0 + (lane >> 2) + (e >> 1) * 8;
                    if (key > row) Sv[nt][e] = -1e30f;
                }
        }

        // ---- online softmax (exp2 domain) ----
#pragma unroll
        for (int h2 = 0; h2 < 2; h2++) {
            float mx = -1e30f;
#pragma unroll
            for (int nt = 0; nt < 8; nt++)
                mx = fmaxf(mx, fmaxf(Sv[nt][h2 * 2], Sv[nt][h2 * 2 + 1]));
            mx = fmaxf(mx, __shfl_xor_sync(0xffffffffu, mx, 1));
            mx = fmaxf(mx, __shfl_xor_sync(0xffffffffu, mx, 2));
            float mnew = fmaxf(mrow[h2], mx);
            float corr = exp2f(mrow[h2] - mnew);
            mrow[h2] = mnew;

            float ls = 0.f;
#pragma unroll
            for (int nt = 0; nt < 8; nt++) {
                float p0 = exp2f(Sv[nt][h2 * 2]     - mnew);
                float p1 = exp2f(Sv[nt][h2 * 2 + 1] - mnew);
                Sv[nt][h2 * 2]     = p0;
                Sv[nt][h2 * 2 + 1] = p1;
                ls += p0 + p1;
            }
            ls += __shfl_xor_sync(0xffffffffu, ls, 1);
            ls += __shfl_xor_sync(0xffffffffu, ls, 2);
            lrow[h2] = lrow[h2] * corr + ls;
#pragma unroll
            for (int nt = 0; nt < 8; nt++) {
                Ov[nt][h2 * 2]     *= corr;
                Ov[nt][h2 * 2 + 1] *= corr;
            }
        }

        // ---- O += P V (3-term split) ----
#pragma unroll
        for (int ks = 0; ks < 4; ks++) {
            uint32_t ph[4], pl[4];
            split2(Sv[2 * ks][0],     Sv[2 * ks][1],     ph[0], pl[0]);
            split2(Sv[2 * ks][2],     Sv[2 * ks][3],     ph[1], pl[1]);
            split2(Sv[2 * ks + 1][0], Sv[2 * ks + 1][1], ph[2], pl[2]);
            split2(Sv[2 * ks + 1][2], Sv[2 * ks + 1][3], ph[3], pl[3]);
#pragma unroll
            for (int nt = 0; nt < 8; nt++) {
                uint32_t voff = (uint32_t)(ks * 16 * LDQS + nt * 8) * 2u;
                uint32_t vh0, vh1, vl0, vl1;
                ldsm_x2_trans(vh0, vh1, v_hi_base + voff);
                ldsm_x2_trans(vl0, vl1, v_lo_base + voff);
                mma16816(Ov[nt], ph, vh0, vh1);
                mma16816(Ov[nt], ph, vl0, vl1);
                mma16816(Ov[nt], pl, vh0, vh1);
            }
        }
    }

    // ---- epilogue: Y = O / l, written pre-split for the proj GEMM ----
    const int b = bh >> 4;
    const int h = bh & 15;
    float inv0 = 1.f / lrow[0];
    float inv1 = 1.f / lrow[1];
#pragma unroll
    for (int h2 = 0; h2 < 2; h2++) {
        float inv = h2 ? inv1 : inv0;
        size_t t = (size_t)qw0 + (lane >> 2) + h2 * 8;
        size_t base = ((size_t)b * T_SEQ + t) * NDIM + h * DH + (lane & 3) * 2;
#pragma unroll
        for (int nt = 0; nt < 8; nt++) {
            uint32_t hi, lo;
            split2(Ov[nt][h2 * 2] * inv, Ov[nt][h2 * 2 + 1] * inv, hi, lo);
            *(uint32_t*)&g_Yh[base + nt * 8] = hi;
            *(uint32_t*)&g_Yl[base + nt * 8] = lo;
        }
    }
}

// ---------------------------------------------------------------------------
extern "C" void kernel_launch(void* const* d_in, const int* in_sizes, int n_in,
                              void* d_out, int out_size)
{
    (void)in_sizes; (void)n_in; (void)out_size;
    const float* x      = (const float*)d_in[0];   // [4,2048,1024]
    const float* W_attn = (const float*)d_in[1];   // [1024,3072]
    const float* b_attn = (const float*)d_in[2];   // [3072]
    const float* W_proj = (const float*)d_in[3];   // [1024,1024]
    const float* b_proj = (const float*)d_in[4];   // [1024]
    float* out = (float*)d_out;                    // [4,2048,1024]

    cudaFuncSetAttribute(attn_mma_kernel,
                         cudaFuncAttributeMaxDynamicSharedMemorySize, ATTN_SMEM);
    cudaFuncSetAttribute(mma_gemm<QKV_N, 0>,
                         cudaFuncAttributeMaxDynamicSharedMemorySize, GEMM_SMEM);
    cudaFuncSetAttribute(mma_gemm<NDIM, 1>,
                         cudaFuncAttributeMaxDynamicSharedMemorySize, GEMM_SMEM);

    // 0) one-shot fp32 -> bf16 hi/lo splits
    split_src<0><<<(M_ROWS * K_DIM / 4 + 255) / 256, 256>>>(x,      M_ROWS * K_DIM / 4);
    split_src<1><<<(K_DIM * QKV_N / 4 + 255) / 256, 256>>>(W_attn, K_DIM * QKV_N / 4);
    split_src<2><<<(K_DIM * NDIM / 4 + 255) / 256, 256>>>(W_proj, K_DIM * NDIM / 4);

    // 1) QKV GEMM (pipelined) + split-scatter to g_Q/g_K/g_V
    mma_gemm<QKV_N, 0><<<dim3(QKV_N / 128, M_ROWS / 128), 256, GEMM_SMEM>>>(
        b_attn, nullptr);

    // 2) Causal flash attention (tensor cores, double-buffered K/V)
    attn_mma_kernel<<<dim3(T_SEQ / 128, BH_TOT), 256, ATTN_SMEM>>>();

    // 3) Output projection (pipelined)
    mma_gemm<NDIM, 1><<<dim3(NDIM / 128, M_ROWS / 128), 256, GEMM_SMEM>>>(
        b_proj, out);
}